// round 2
// baseline (speedup 1.0000x reference)
#include <cuda_runtime.h>

#define NN 100000
#define EE 800000
#define DD 64
#define TOT (EE + NN)
#define ROUNDS 4

// ---------------- scratch (device globals: no runtime allocation) ----------
__device__ float g_h[NN * DD];     // h = x @ W
__device__ float g_xa[NN * DD];    // ping
__device__ float g_xb[NN * DD];    // pong
__device__ int   g_rowptr[NN + 1];
__device__ int   g_cur[NN];        // degree, then fill cursor
__device__ float g_dis[NN];        // deg^-1/2
__device__ int   g_src[TOT];       // CSR-by-dst: source node per entry
__device__ float g_nrm[TOT];       // CSR-by-dst: edge weight per entry
__device__ int   g_bsum[128];
__device__ int   g_boff[128];

// ---------------- helpers ---------------------------------------------------
__device__ __forceinline__ int warp_incl_scan(int x) {
    int lane = threadIdx.x & 31;
#pragma unroll
    for (int o = 1; o < 32; o <<= 1) {
        int t = __shfl_up_sync(0xffffffffu, x, o);
        if (lane >= o) x += t;
    }
    return x;
}

// ---------------- CSR build -------------------------------------------------
__global__ void k_init() {
    int i = blockIdx.x * 256 + threadIdx.x;
    if (i < NN) g_cur[i] = 1;  // self loop
}

__global__ void k_count(const int* __restrict__ ei) {
    int e = blockIdx.x * 256 + threadIdx.x;
    if (e < EE) atomicAdd(&g_cur[ei[EE + e]], 1);  // dst row of edge_index
}

__global__ void k_dis() {
    int i = blockIdx.x * 256 + threadIdx.x;
    if (i < NN) g_dis[i] = rsqrtf((float)g_cur[i]);  // deg >= 1 always
}

__global__ void k_scan_block() {  // grid = ceil(NN/1024), block 1024
    __shared__ int ws[32];
    int i = blockIdx.x * 1024 + threadIdx.x;
    int lane = threadIdx.x & 31, wid = threadIdx.x >> 5;
    int v = (i < NN) ? g_cur[i] : 0;
    int inc = warp_incl_scan(v);
    if (lane == 31) ws[wid] = inc;
    __syncthreads();
    if (wid == 0) {
        int s = ws[lane];
        s = warp_incl_scan(s);
        ws[lane] = s;
    }
    __syncthreads();
    int base = wid ? ws[wid - 1] : 0;
    if (i < NN) g_rowptr[i] = base + inc - v;  // exclusive, local to block
    if (threadIdx.x == 1023) g_bsum[blockIdx.x] = base + inc;  // block total
}

__global__ void k_scan_top(int B) {  // 1 block, 128 threads
    __shared__ int ws[4];
    int tid = threadIdx.x, lane = tid & 31, wid = tid >> 5;
    int v = (tid < B) ? g_bsum[tid] : 0;
    int inc = warp_incl_scan(v);
    if (lane == 31) ws[wid] = inc;
    __syncthreads();
    if (tid == 0) {
        int a = ws[0], b = ws[1], c = ws[2];
        ws[0] = 0; ws[1] = a; ws[2] = a + b; ws[3] = a + b + c;
    }
    __syncthreads();
    if (tid < B) g_boff[tid] = ws[wid] + inc - v;  // exclusive across blocks
}

__global__ void k_addoff() {
    int i = blockIdx.x * 256 + threadIdx.x;
    if (i < NN) {
        int v = g_rowptr[i] + g_boff[i >> 10];
        g_rowptr[i] = v;
        g_cur[i] = v;  // cursor for fill
    }
    if (i == 0) g_rowptr[NN] = TOT;
}

__global__ void k_fill(const int* __restrict__ ei) {
    int t = blockIdx.x * 256 + threadIdx.x;
    if (t >= TOT) return;
    int s, d;
    if (t < EE) { s = ei[t]; d = ei[EE + t]; }
    else        { s = d = t - EE; }        // self loop
    int pos = atomicAdd(&g_cur[d], 1);
    g_src[pos] = s;
    g_nrm[pos] = g_dis[s] * g_dis[d];
}

// ---------------- GEMM: H[N,64] = X[N,64] @ W[64,64], fp32 via FFMA2 --------
// Input selector: 0 = external x, 1 = g_xa, 2 = g_xb. Output always g_h.
// 64 threads/block, 64-row tile. Micro-tile: 8 rows x 8 cols (4 f32x2 pairs).
// Column pairs are strided (tc, tc+8, tc+16, tc+24) for conflict-free LDS.64.
__global__ void __launch_bounds__(64) k_gemm(const float* __restrict__ Xext,
                                             int in_sel,
                                             const float* __restrict__ Wg) {
    __shared__ __align__(16) float Ws[64 * 64];
    __shared__ __align__(16) float Xs[64 * 65];  // stride 65: row -> distinct bank
    int tid = threadIdx.x;

    const float* X = (in_sel == 0) ? Xext : (in_sel == 1 ? g_xa : g_xb);

    const float4* W4 = (const float4*)Wg;
    float4* Ws4 = (float4*)Ws;
#pragma unroll
    for (int i = tid; i < 1024; i += 64) Ws4[i] = W4[i];

    int row0 = blockIdx.x * 64;
    for (int t = tid; t < 1024; t += 64) {
        int r = t >> 4, c4 = t & 15;
        float4 v;
        if (row0 + r < NN) v = ((const float4*)X)[(size_t)(row0 + r) * 16 + c4];
        else v = make_float4(0.f, 0.f, 0.f, 0.f);
        float* p = &Xs[r * 65 + c4 * 4];
        p[0] = v.x; p[1] = v.y; p[2] = v.z; p[3] = v.w;
    }
    __syncthreads();

    int tr = tid >> 3;  // 0..7 -> rows tr*8..tr*8+7
    int tc = tid & 7;   // 0..7 -> col pairs {tc, tc+8, tc+16, tc+24}

    unsigned long long acc[8][4];
#pragma unroll
    for (int r = 0; r < 8; r++)
#pragma unroll
        for (int c = 0; c < 4; c++) acc[r][c] = 0ull;

#pragma unroll 4
    for (int k = 0; k < 64; k++) {
        unsigned long long wv[4];
#pragma unroll
        for (int c = 0; c < 4; c++)
            wv[c] = *(const unsigned long long*)&Ws[k * 64 + 2 * (tc + 8 * c)];
        unsigned long long xp[8];
#pragma unroll
        for (int r = 0; r < 8; r++) {
            unsigned u = __float_as_uint(Xs[(tr * 8 + r) * 65 + k]);
            asm("mov.b64 %0, {%1, %1};" : "=l"(xp[r]) : "r"(u));
        }
#pragma unroll
        for (int r = 0; r < 8; r++)
#pragma unroll
            for (int c = 0; c < 4; c++)
                asm("fma.rn.f32x2 %0, %1, %2, %0;"
                    : "+l"(acc[r][c]) : "l"(xp[r]), "l"(wv[c]));
    }

    float2* Hp = (float2*)g_h;
#pragma unroll
    for (int r = 0; r < 8; r++) {
        int row = row0 + tr * 8 + r;
        if (row < NN) {
#pragma unroll
            for (int c = 0; c < 4; c++) {
                float2 v;
                asm("mov.b64 {%0, %1}, %2;" : "=f"(v.x), "=f"(v.y) : "l"(acc[r][c]));
                Hp[(size_t)row * 32 + tc + 8 * c] = v;
            }
        }
    }
}

// ---------------- fused gather-aggregate + bias + LayerNorm -----------------
// One warp per destination node; lane owns features {2*lane, 2*lane+1}.
// Output selector: 0 = g_xa, 1 = g_xb, 2 = external out.
__global__ void __launch_bounds__(256) k_agg(const float* __restrict__ bb,
                                             const float* __restrict__ gm,
                                             const float* __restrict__ bt,
                                             float* __restrict__ out_ext,
                                             int out_sel) {
    int w = (blockIdx.x * 256 + threadIdx.x) >> 5;
    int lane = threadIdx.x & 31;
    if (w >= NN) return;

    float* out = (out_sel == 0) ? g_xa : (out_sel == 1 ? g_xb : out_ext);

    int s0 = g_rowptr[w], s1 = g_rowptr[w + 1];
    const float2* h2 = (const float2*)g_h;
    float ax = 0.f, ay = 0.f;
    for (int j = s0; j < s1; j++) {
        int s = g_src[j];
        float wt = g_nrm[j];
        float2 hv = h2[(size_t)s * 32 + lane];
        ax = fmaf(hv.x, wt, ax);
        ay = fmaf(hv.y, wt, ay);
    }
    ax += bb[lane * 2];
    ay += bb[lane * 2 + 1];

    float sum = ax + ay;
    float sq = ax * ax + ay * ay;
#pragma unroll
    for (int o = 16; o; o >>= 1) {
        sum += __shfl_xor_sync(0xffffffffu, sum, o);
        sq  += __shfl_xor_sync(0xffffffffu, sq, o);
    }
    float mu = sum * (1.0f / 64.0f);
    float var = sq * (1.0f / 64.0f) - mu * mu;
    float inv = rsqrtf(var + 1e-5f);

    float2 o2;
    o2.x = (ax - mu) * inv * gm[lane * 2] + bt[lane * 2];
    o2.y = (ay - mu) * inv * gm[lane * 2 + 1] + bt[lane * 2 + 1];
    ((float2*)out)[(size_t)w * 32 + lane] = o2;
}

// ---------------- launch ----------------------------------------------------
extern "C" void kernel_launch(void* const* d_in, const int* in_sizes, int n_in,
                              void* d_out, int out_size) {
    const float* x  = (const float*)d_in[0];
    const int*   ei = (const int*)d_in[1];
    const float* W  = (const float*)d_in[2];
    const float* b  = (const float*)d_in[3];
    const float* gm = (const float*)d_in[4];
    const float* bt = (const float*)d_in[5];
    float* out = (float*)d_out;

    // CSR build (once per launch, reused by all 4 rounds)
    k_init<<<(NN + 255) / 256, 256>>>();
    k_count<<<(EE + 255) / 256, 256>>>(ei);
    k_dis<<<(NN + 255) / 256, 256>>>();
    int B = (NN + 1023) / 1024;
    k_scan_block<<<B, 1024>>>();
    k_scan_top<<<1, 128>>>(B);
    k_addoff<<<(NN + 255) / 256, 256>>>();
    k_fill<<<(TOT + 255) / 256, 256>>>(ei);

    // round r: gemm reads (r==0 ? x : prev out), agg writes round buffer
    // outs: r0 -> g_xa(0), r1 -> g_xb(1), r2 -> g_xa(0), r3 -> external(2)
    const int in_sels[ROUNDS]  = {0, 1, 2, 1};  // x, xa, xb, xa
    const int out_sels[ROUNDS] = {0, 1, 0, 2};  // xa, xb, xa, ext
    for (int r = 0; r < ROUNDS; r++) {
        k_gemm<<<(NN + 63) / 64, 64>>>(x, in_sels[r], W);
        k_agg<<<(NN * 32 + 255) / 256, 256>>>(b, gm, bt, out, out_sels[r]);
    }
}